// round 1
// baseline (speedup 1.0000x reference)
#include <cuda_runtime.h>

#define CK_B 4
#define CK_N 8192
#define CK_C 512
#define CK_H 8
#define CK_D 64
#define CK_KCH 16
#define CK_SCALE 0.125f

// ---------------- device scratch (allocation-free: __device__ globals) ----------------
__device__ float g_G [CK_B * CK_C * CK_C];   // per-batch Gram matrix x^T ctx
__device__ float g_T1[CK_B * CK_C * CK_C];   // Wq * G
__device__ float g_PA[CK_B * CK_C * CK_C];   // proj * blockdiag(att)
__device__ float g_M [CK_B * CK_C * CK_C];   // PA * Wv
__device__ float g_att[CK_B * CK_H * CK_D * CK_D];
__device__ float g_sx  [CK_B * CK_C];
__device__ float g_sctx[CK_B * CK_C];
__device__ float g_r   [CK_B * CK_C];

// ---------------- zero the accumulated buffers (every replay) ----------------
__global__ void k_zero() {
    int idx = blockIdx.x * blockDim.x + threadIdx.x;
    int stride = gridDim.x * blockDim.x;
    for (int i = idx; i < CK_B * CK_C * CK_C; i += stride) g_G[i] = 0.0f;
    if (idx < CK_B * CK_C) { g_sx[idx] = 0.0f; g_sctx[idx] = 0.0f; }
}

// ---------------- G_b = x_b^T * ctx_b  (split-K over N, atomic accumulate) ----------
// grid: (ctile=4, c'tile=4, b*KCH) ; 256 threads ; 128x128 tile, 8x8 per thread
__global__ __launch_bounds__(256) void k_G(const float* __restrict__ x,
                                           const float* __restrict__ ctx) {
    __shared__ float As[8][128];
    __shared__ float Bs[8][128];
    const int cbase  = blockIdx.x * 128;
    const int cpbase = blockIdx.y * 128;
    const int b  = blockIdx.z / CK_KCH;
    const int kc = blockIdx.z % CK_KCH;
    const float* xb = x   + (size_t)b * CK_N * CK_C;
    const float* cb = ctx + (size_t)b * CK_N * CK_C;
    const int tid = threadIdx.x;
    const int lr = tid >> 5;            // 0..7   (n row within 8-chunk)
    const int lc = (tid & 31) << 2;     // 0..124 (col, float4)
    const int tx = tid & 15, ty = tid >> 4;
    float acc[8][8];
#pragma unroll
    for (int i = 0; i < 8; i++)
#pragma unroll
        for (int j = 0; j < 8; j++) acc[i][j] = 0.0f;
    float4 sxa = make_float4(0.f, 0.f, 0.f, 0.f);
    float4 sca = make_float4(0.f, 0.f, 0.f, 0.f);
    const int nbase = kc * (CK_N / CK_KCH);
    for (int k0 = 0; k0 < CK_N / CK_KCH; k0 += 8) {
        float4 av = *(const float4*)(xb + (size_t)(nbase + k0 + lr) * CK_C + cbase  + lc);
        float4 bv = *(const float4*)(cb + (size_t)(nbase + k0 + lr) * CK_C + cpbase + lc);
        sxa.x += av.x; sxa.y += av.y; sxa.z += av.z; sxa.w += av.w;
        sca.x += bv.x; sca.y += bv.y; sca.z += bv.z; sca.w += bv.w;
        __syncthreads();
        *(float4*)&As[lr][lc] = av;
        *(float4*)&Bs[lr][lc] = bv;
        __syncthreads();
#pragma unroll
        for (int kk = 0; kk < 8; kk++) {
            float a[8], b2[8];
#pragma unroll
            for (int i = 0; i < 8; i++) a[i]  = As[kk][ty + 16 * i];
#pragma unroll
            for (int j = 0; j < 8; j++) b2[j] = Bs[kk][tx + 16 * j];
#pragma unroll
            for (int i = 0; i < 8; i++)
#pragma unroll
                for (int j = 0; j < 8; j++) acc[i][j] += a[i] * b2[j];
        }
    }
    float* Gb = g_G + (size_t)b * CK_C * CK_C;
#pragma unroll
    for (int i = 0; i < 8; i++) {
        const int c = cbase + ty + 16 * i;
#pragma unroll
        for (int j = 0; j < 8; j++)
            atomicAdd(&Gb[(size_t)c * CK_C + cpbase + tx + 16 * j], acc[i][j]);
    }
    if (blockIdx.y == 0) {  // each (n,c) element counted exactly once across remaining blocks
        atomicAdd(&g_sx[b * CK_C + cbase + lc + 0], sxa.x);
        atomicAdd(&g_sx[b * CK_C + cbase + lc + 1], sxa.y);
        atomicAdd(&g_sx[b * CK_C + cbase + lc + 2], sxa.z);
        atomicAdd(&g_sx[b * CK_C + cbase + lc + 3], sxa.w);
    }
    if (blockIdx.x == 0) {
        atomicAdd(&g_sctx[b * CK_C + cpbase + lc + 0], sca.x);
        atomicAdd(&g_sctx[b * CK_C + cpbase + lc + 1], sca.y);
        atomicAdd(&g_sctx[b * CK_C + cpbase + lc + 2], sca.z);
        atomicAdd(&g_sctx[b * CK_C + cpbase + lc + 3], sca.w);
    }
}

// ---------------- generic 512x512x512 row-major GEMM body (64x64 tile, 4x4/thread) ---
__device__ __forceinline__ void gemm512_body(const float* __restrict__ A,
                                             const float* __restrict__ Bm,
                                             float* __restrict__ Co) {
    __shared__ float As[64][20];   // [m][k], padded for alignment + banks
    __shared__ float Bs[16][64];   // [k][n]
    const int mbase = blockIdx.x * 64;
    const int nbase = blockIdx.y * 64;
    const int tid = threadIdx.x;
    const int tx = tid & 15, ty = tid >> 4;
    const int ar = tid >> 2,  ac = (tid & 3)  << 2;   // A loader: 64 rows x 16 cols
    const int br = tid >> 4,  bc = (tid & 15) << 2;   // B loader: 16 rows x 64 cols
    float acc[4][4];
#pragma unroll
    for (int i = 0; i < 4; i++)
#pragma unroll
        for (int j = 0; j < 4; j++) acc[i][j] = 0.0f;
    for (int k0 = 0; k0 < CK_C; k0 += 16) {
        float4 av = *(const float4*)(A  + (size_t)(mbase + ar) * CK_C + k0 + ac);
        float4 bv = *(const float4*)(Bm + (size_t)(k0 + br) * CK_C + nbase + bc);
        __syncthreads();
        *(float4*)&As[ar][ac] = av;
        *(float4*)&Bs[br][bc] = bv;
        __syncthreads();
#pragma unroll
        for (int kk = 0; kk < 16; kk++) {
            float a[4], b2[4];
#pragma unroll
            for (int i = 0; i < 4; i++) a[i]  = As[ty + 16 * i][kk];
#pragma unroll
            for (int j = 0; j < 4; j++) b2[j] = Bs[kk][tx + 16 * j];
#pragma unroll
            for (int i = 0; i < 4; i++)
#pragma unroll
                for (int j = 0; j < 4; j++) acc[i][j] += a[i] * b2[j];
        }
    }
#pragma unroll
    for (int i = 0; i < 4; i++)
#pragma unroll
        for (int j = 0; j < 4; j++)
            Co[(size_t)(mbase + ty + 16 * i) * CK_C + nbase + tx + 16 * j] = acc[i][j];
}

// T1_b = Wq * G_b   (grid (8,8,B))
__global__ __launch_bounds__(256) void k_T1(const float* __restrict__ Wq) {
    gemm512_body(Wq, g_G + (size_t)blockIdx.z * CK_C * CK_C,
                 g_T1 + (size_t)blockIdx.z * CK_C * CK_C);
}
// M_b = PA_b * Wv   (grid (8,8,B))
__global__ __launch_bounds__(256) void k_M(const float* __restrict__ Wv) {
    gemm512_body(g_PA + (size_t)blockIdx.z * CK_C * CK_C, Wv,
                 g_M + (size_t)blockIdx.z * CK_C * CK_C);
}

// ---------------- att_pre + bias terms + softmax, per (b,h)  (grid (H,B)) ------------
__global__ __launch_bounds__(256) void k_att(const float* __restrict__ Wk,
                                             const float* __restrict__ Wq,
                                             const float* __restrict__ bq,
                                             const float* __restrict__ bk,
                                             float* __restrict__ out_att) {
    __shared__ float T1s[64][20];
    __shared__ float Wks[64][20];
    __shared__ float S[64][65];
    __shared__ float qrow[64], krow[64], bqs[64], bks[64];
    const int h = blockIdx.x;
    const int b = blockIdx.y;
    const int o0 = h * CK_D;
    const int tid = threadIdx.x;
    const int tx = tid & 15, ty = tid >> 4;
    const float* T1b = g_T1 + (size_t)b * CK_C * CK_C;

    if (tid < 64) {                    // qrow[d] = sum_c sx[c] * Wq[o0+d, c]
        float s = 0.0f;
        const float* wr = Wq + (size_t)(o0 + tid) * CK_C;
        const float* sx = g_sx + b * CK_C;
        for (int c = 0; c < CK_C; c++) s += sx[c] * wr[c];
        qrow[tid] = s;
    } else if (tid < 128) {            // krow[e] = sum_c sctx[c] * Wk[o0+e, c]
        const int e = tid - 64;
        float s = 0.0f;
        const float* wr = Wk + (size_t)(o0 + e) * CK_C;
        const float* sc = g_sctx + b * CK_C;
        for (int c = 0; c < CK_C; c++) s += sc[c] * wr[c];
        krow[e] = s;
    } else if (tid < 192) {
        bqs[tid - 128] = bq[o0 + tid - 128];
    } else {
        bks[tid - 192] = bk[o0 + tid - 192];
    }

    float acc[4][4];
#pragma unroll
    for (int i = 0; i < 4; i++)
#pragma unroll
        for (int j = 0; j < 4; j++) acc[i][j] = 0.0f;
    const int r = tid >> 2, c4 = (tid & 3) << 2;
    for (int k0 = 0; k0 < CK_C; k0 += 16) {
        float4 av = *(const float4*)(T1b + (size_t)(o0 + r) * CK_C + k0 + c4);
        float4 bv = *(const float4*)(Wk  + (size_t)(o0 + r) * CK_C + k0 + c4);
        __syncthreads();
        *(float4*)&T1s[r][c4] = av;
        *(float4*)&Wks[r][c4] = bv;
        __syncthreads();
#pragma unroll
        for (int kk = 0; kk < 16; kk++) {
            float a[4], b2[4];
#pragma unroll
            for (int i = 0; i < 4; i++) a[i]  = T1s[ty + 16 * i][kk];
#pragma unroll
            for (int j = 0; j < 4; j++) b2[j] = Wks[tx + 16 * j][kk];
#pragma unroll
            for (int i = 0; i < 4; i++)
#pragma unroll
                for (int j = 0; j < 4; j++) acc[i][j] += a[i] * b2[j];
        }
    }
    __syncthreads();
#pragma unroll
    for (int i = 0; i < 4; i++) {
        const int d = ty + 16 * i;
#pragma unroll
        for (int j = 0; j < 4; j++) {
            const int e = tx + 16 * j;
            S[d][e] = CK_SCALE * (acc[i][j] + bqs[d] * krow[e] + bks[e] * qrow[d]
                                  + (float)CK_N * bqs[d] * bks[e]);
        }
    }
    __syncthreads();
    if (tid < 64) {                    // softmax over e per row d, then store att
        const int d = tid;
        float m = -1e30f;
        for (int e = 0; e < 64; e++) m = fmaxf(m, S[d][e]);
        float s = 0.0f;
        for (int e = 0; e < 64; e++) { float p = expf(S[d][e] - m); S[d][e] = p; s += p; }
        const float inv = 1.0f / s;
        float* ga = g_att + (((size_t)b * CK_H + h) * CK_D + d) * CK_D;
        for (int e = 0; e < 64; e++) {
            const float a = S[d][e] * inv;
            ga[e] = a;
            if (out_att) out_att[(((size_t)b * CK_H + h) * CK_D + d) * CK_D + e] = a;
        }
    }
}

// ---------------- PA_b[j, h*64+e] = sum_d proj[j, h*64+d] * att[b,h,d,e] ------------
// grid (jtile=8, H, B)
__global__ __launch_bounds__(256) void k_PA(const float* __restrict__ proj) {
    __shared__ float Ps[64][65];
    __shared__ float At[64][65];
    const int jt = blockIdx.x;
    const int h  = blockIdx.y;
    const int b  = blockIdx.z;
    const int tid = threadIdx.x;
    for (int i = tid; i < 64 * 64; i += 256) {
        const int rr = i >> 6, cc = i & 63;
        Ps[rr][cc] = proj[(size_t)(jt * 64 + rr) * CK_C + h * 64 + cc];
        At[rr][cc] = g_att[(((size_t)b * CK_H + h) * CK_D + rr) * CK_D + cc];
    }
    __syncthreads();
    const int tx = tid & 15, ty = tid >> 4;
    float acc[4][4];
#pragma unroll
    for (int i = 0; i < 4; i++)
#pragma unroll
        for (int j = 0; j < 4; j++) acc[i][j] = 0.0f;
    for (int d = 0; d < 64; d++) {
        float p[4], a2[4];
#pragma unroll
        for (int i = 0; i < 4; i++) p[i]  = Ps[ty + 16 * i][d];
#pragma unroll
        for (int j = 0; j < 4; j++) a2[j] = At[d][tx + 16 * j];
#pragma unroll
        for (int i = 0; i < 4; i++)
#pragma unroll
            for (int j = 0; j < 4; j++) acc[i][j] += p[i] * a2[j];
    }
    float* PAb = g_PA + (size_t)b * CK_C * CK_C;
#pragma unroll
    for (int i = 0; i < 4; i++)
#pragma unroll
        for (int j = 0; j < 4; j++)
            PAb[(size_t)(jt * 64 + ty + 16 * i) * CK_C + h * 64 + tx + 16 * j] = acc[i][j];
}

// ---------------- r_b[j] = PA_b[j,:] . bv + pb[j]   (grid B, 512 threads) -----------
__global__ void k_r(const float* __restrict__ bv, const float* __restrict__ pb) {
    const int b = blockIdx.x;
    const int j = threadIdx.x;
    const float* row = g_PA + ((size_t)b * CK_C + j) * CK_C;
    float s = pb[j];
    for (int o = 0; o < CK_C; o++) s += row[o] * bv[o];
    g_r[b * CK_C + j] = s;
}

// ---------------- Y_b = ctx_b * M_b^T + r_b   (grid (jtile=4, ntile=64, B)) ----------
// 128x128 tile, 8x8 per thread; both operands K-major in gmem -> smem transpose load
__global__ __launch_bounds__(256) void k_final(const float* __restrict__ ctx,
                                               float* __restrict__ Y) {
    __shared__ float As[8][132];
    __shared__ float Bs[8][132];
    const int jbase = blockIdx.x * 128;
    const int nb    = blockIdx.y * 128;
    const int b     = blockIdx.z;
    const float* cb = ctx + (size_t)b * CK_N * CK_C;
    const float* Mb = g_M + (size_t)b * CK_C * CK_C;
    const int tid = threadIdx.x;
    const int lr = tid >> 1;          // 0..127
    const int lc = (tid & 1) << 2;    // 0 or 4
    const int tx = tid & 15, ty = tid >> 4;
    float acc[8][8];
#pragma unroll
    for (int i = 0; i < 8; i++)
#pragma unroll
        for (int j = 0; j < 8; j++) acc[i][j] = 0.0f;
    for (int k0 = 0; k0 < CK_C; k0 += 8) {
        float4 av = *(const float4*)(cb + (size_t)(nb + lr) * CK_C + k0 + lc);
        float4 bv = *(const float4*)(Mb + (size_t)(jbase + lr) * CK_C + k0 + lc);
        __syncthreads();
        As[lc + 0][lr] = av.x; As[lc + 1][lr] = av.y;
        As[lc + 2][lr] = av.z; As[lc + 3][lr] = av.w;
        Bs[lc + 0][lr] = bv.x; Bs[lc + 1][lr] = bv.y;
        Bs[lc + 2][lr] = bv.z; Bs[lc + 3][lr] = bv.w;
        __syncthreads();
#pragma unroll
        for (int kk = 0; kk < 8; kk++) {
            float a[8], b2[8];
#pragma unroll
            for (int i = 0; i < 8; i++) a[i]  = As[kk][ty + 16 * i];
#pragma unroll
            for (int j = 0; j < 8; j++) b2[j] = Bs[kk][tx + 16 * j];
#pragma unroll
            for (int i = 0; i < 8; i++)
#pragma unroll
                for (int j = 0; j < 8; j++) acc[i][j] += a[i] * b2[j];
        }
    }
    float rj[8];
#pragma unroll
    for (int j = 0; j < 8; j++) rj[j] = g_r[b * CK_C + jbase + tx + 16 * j];
#pragma unroll
    for (int i = 0; i < 8; i++) {
        const int n = nb + ty + 16 * i;
#pragma unroll
        for (int j = 0; j < 8; j++)
            Y[((size_t)b * CK_N + n) * CK_C + jbase + tx + 16 * j] = acc[i][j] + rj[j];
    }
}

// ---------------- launch ----------------
extern "C" void kernel_launch(void* const* d_in, const int* in_sizes, int n_in,
                              void* d_out, int out_size) {
    const float* x    = (const float*)d_in[0];
    const float* ctxp = (const float*)d_in[1];
    const float* Wq_w = (const float*)d_in[2];
    const float* Wq_b = (const float*)d_in[3];
    const float* Wk_w = (const float*)d_in[4];
    const float* Wk_b = (const float*)d_in[5];
    const float* Wv_w = (const float*)d_in[6];
    const float* Wv_b = (const float*)d_in[7];
    const float* Pw   = (const float*)d_in[8];
    const float* Pb   = (const float*)d_in[9];
    float* out = (float*)d_out;

    const int out_elems = CK_B * CK_N * CK_C;            // 16777216
    const int att_elems = CK_B * CK_H * CK_D * CK_D;     // 131072
    float* att_out = (out_size >= out_elems + att_elems) ? (out + (size_t)out_elems)
                                                         : (float*)0;

    k_zero <<<512, 256>>>();
    k_G    <<<dim3(4, 4, CK_B * CK_KCH), 256>>>(x, ctxp);
    k_T1   <<<dim3(8, 8, CK_B), 256>>>(Wq_w);
    k_att  <<<dim3(CK_H, CK_B), 256>>>(Wk_w, Wq_w, Wq_b, Wk_b, att_out);
    k_PA   <<<dim3(8, CK_H, CK_B), 256>>>(Pw);
    k_M    <<<dim3(8, 8, CK_B), 256>>>(Wv_w);
    k_r    <<<CK_B, CK_C>>>(Wv_b, Pb);
    k_final<<<dim3(4, 64, CK_B), 256>>>(ctxp, out);
}

// round 4
// speedup vs baseline: 1.3259x; 1.3259x over previous
#include <cuda_runtime.h>
#include <cuda_bf16.h>
#include <cstdint>

#define CK_B 4
#define CK_N 8192
#define CK_C 512
#define CK_H 8
#define CK_D 64
#define CK_SCALE 0.125f
#define KSPLIT 4

// ---------------- device scratch ----------------
__device__ float g_G [CK_B * CK_C * CK_C];
__device__ float g_Gpart[KSPLIT * CK_B * CK_C * CK_C];
__device__ float g_T1[CK_B * CK_C * CK_C];
__device__ float g_PA[CK_B * CK_C * CK_C];
__device__ float g_att[CK_B * CK_H * CK_D * CK_D];
__device__ float g_sx[CK_B * CK_C], g_sctx[CK_B * CK_C], g_r[CK_B * CK_C];
__device__ float g_qrow[CK_B * CK_C], g_krow[CK_B * CK_C];
// bf16 hi/lo copies
__device__ __nv_bfloat16 g_xT_h[CK_B * CK_C * CK_N];   // [b][c][n]
__device__ __nv_bfloat16 g_xT_l[CK_B * CK_C * CK_N];
__device__ __nv_bfloat16 g_cT_h[CK_B * CK_C * CK_N];   // [b][c'][n]
__device__ __nv_bfloat16 g_cT_l[CK_B * CK_C * CK_N];
__device__ __nv_bfloat16 g_c_h [CK_B * CK_N * CK_C];   // [b][n][c] natural
__device__ __nv_bfloat16 g_c_l [CK_B * CK_N * CK_C];
__device__ __nv_bfloat16 g_M_h [CK_B * CK_C * CK_C];
__device__ __nv_bfloat16 g_M_l [CK_B * CK_C * CK_C];

// ---------------- portable PTX helpers (sm_100 plain, no 'a' features) -------
__device__ __forceinline__ uint32_t smem_u32(const void* p) {
    uint32_t a;
    asm("{ .reg .u64 t; cvta.to.shared.u64 t, %1; cvt.u32.u64 %0, t; }" : "=r"(a) : "l"(p));
    return a;
}
__device__ __forceinline__ uint32_t sw128(uint32_t o) { return o ^ ((o >> 3) & 0x70); }
__device__ __forceinline__ void cp_async16(uint32_t dst, const void* src) {
    asm volatile("cp.async.cg.shared.global [%0], [%1], 16;" :: "r"(dst), "l"(src));
}
__device__ __forceinline__ void cp_commit() { asm volatile("cp.async.commit_group;" ::: "memory"); }
template <int N> __device__ __forceinline__ void cp_wait() {
    asm volatile("cp.async.wait_group %0;" :: "n"(N) : "memory");
}
__device__ __forceinline__ void ldsm4(uint32_t* r, uint32_t addr) {
    asm volatile("ldmatrix.sync.aligned.m8n8.x4.shared.b16 {%0,%1,%2,%3}, [%4];"
                 : "=r"(r[0]), "=r"(r[1]), "=r"(r[2]), "=r"(r[3]) : "r"(addr));
}
__device__ __forceinline__ void mma16816(float* c, const uint32_t* a, uint32_t b0, uint32_t b1) {
    asm volatile("mma.sync.aligned.m16n8k16.row.col.f32.bf16.bf16.f32 "
                 "{%0,%1,%2,%3}, {%4,%5,%6,%7}, {%8,%9}, {%0,%1,%2,%3};"
                 : "+f"(c[0]), "+f"(c[1]), "+f"(c[2]), "+f"(c[3])
                 : "r"(a[0]), "r"(a[1]), "r"(a[2]), "r"(a[3]), "r"(b0), "r"(b1));
}

// smem: double buffer, each 96KB: Ah(16K) Al(16K) Bh(32K) Bl(32K)
#define BUF_STRIDE 98304
#define OFF_AL 16384
#define OFF_BH 32768
#define OFF_BL 65536
#define SMEM_MMA (2 * BUF_STRIDE)

// stage one K=64 chunk: A 128 rows, B 256 rows (bf16, K-major, ld in elems)
__device__ __forceinline__ void issue_chunk(uint32_t sbuf,
        const __nv_bfloat16* __restrict__ Ah, const __nv_bfloat16* __restrict__ Al, size_t ldA,
        const __nv_bfloat16* __restrict__ Bh, const __nv_bfloat16* __restrict__ Bl, size_t ldB,
        int coloff, int tid) {
    for (int u = tid; u < 6144; u += 512) {
        const __nv_bfloat16* src;
        uint32_t dst;
        if (u < 2048) {
            const int row = (u & 1023) >> 3, s = u & 7;
            src = (u < 1024 ? Ah : Al) + (size_t)row * ldA + coloff + s * 8;
            dst = sbuf + (u < 1024 ? 0 : OFF_AL) + sw128(row * 128 + s * 16);
        } else {
            const int v = u - 2048;
            const int row = (v & 2047) >> 3, s = v & 7;
            src = (v < 2048 ? Bh : Bl) + (size_t)row * ldB + coloff + s * 8;
            dst = sbuf + (v < 2048 ? OFF_BH : OFF_BL) + sw128(row * 128 + s * 16);
        }
        cp_async16(dst, src);
    }
    cp_commit();
}

// 3-pass split-bf16 compute over one staged chunk. warp tile 32m x 64n.
__device__ __forceinline__ void compute_chunk(uint32_t sbuf, int wm, int wn, int lane,
                                              float acc[2][8][4]) {
    const int arow = (lane & 7) + ((lane >> 3) & 1) * 8;
    const int acol = (lane >> 4) * 16;
    const int brow = (lane & 7) + (lane >> 4) * 8;
    const int bcol = ((lane >> 3) & 1) * 16;
#pragma unroll
    for (int p = 0; p < 3; p++) {
        const uint32_t Ab = sbuf + (p < 2 ? 0 : OFF_AL);
        const uint32_t Bb = sbuf + (p == 1 ? OFF_BL : OFF_BH);
#pragma unroll
        for (int k16 = 0; k16 < 4; k16++) {
            uint32_t a[2][4], bf[4][4];
#pragma unroll
            for (int mt = 0; mt < 2; mt++) {
                const int row = (wm * 2 + mt) * 16 + arow;
                ldsm4(a[mt], Ab + sw128(row * 128 + k16 * 32 + acol));
            }
#pragma unroll
            for (int np = 0; np < 4; np++) {
                const int row = (wn * 4 + np) * 16 + brow;
                ldsm4(bf[np], Bb + sw128(row * 128 + k16 * 32 + bcol));
            }
#pragma unroll
            for (int mt = 0; mt < 2; mt++)
#pragma unroll
                for (int np = 0; np < 4; np++) {
                    mma16816(acc[mt][np * 2 + 0], a[mt], bf[np][0], bf[np][1]);
                    mma16816(acc[mt][np * 2 + 1], a[mt], bf[np][2], bf[np][3]);
                }
        }
    }
}

// ---------------- tiny zero ----------------
__global__ void k_zero() {
    int i = blockIdx.x * 256 + threadIdx.x;
    if (i < CK_B * CK_C) { g_sx[i] = 0.0f; g_sctx[i] = 0.0f; }
}

// ---------------- fp32 -> bf16 hi/lo conversions ----------------
__global__ __launch_bounds__(256) void conv_x(const float* __restrict__ x) {
    __shared__ __nv_bfloat16 sh[64 * 66], sl[64 * 66];
    __shared__ float ssum[64];
    const int b = blockIdx.z, n0 = blockIdx.x * 64, c0 = blockIdx.y * 64;
    const int tid = threadIdx.x;
    if (tid < 64) ssum[tid] = 0.0f;
    __syncthreads();
    for (int i = tid; i < 4096; i += 256) {
        const int n = i >> 6, c = i & 63;
        float v = x[((size_t)b * CK_N + n0 + n) * CK_C + c0 + c];
        __nv_bfloat16 h = __float2bfloat16(v);
        __nv_bfloat16 l = __float2bfloat16(v - __bfloat162float(h));
        sh[c * 66 + n] = h; sl[c * 66 + n] = l;
        atomicAdd(&ssum[c], v);
    }
    __syncthreads();
    for (int i = tid; i < 4096; i += 256) {
        const int c = i >> 6, n = i & 63;
        const size_t o = ((size_t)b * CK_C + c0 + c) * CK_N + n0 + n;
        g_xT_h[o] = sh[c * 66 + n]; g_xT_l[o] = sl[c * 66 + n];
    }
    if (tid < 64) atomicAdd(&g_sx[b * CK_C + c0 + tid], ssum[tid]);
}

__global__ __launch_bounds__(256) void conv_ctx(const float* __restrict__ ctx) {
    __shared__ __nv_bfloat16 sh[64 * 66], sl[64 * 66];
    __shared__ float ssum[64];
    const int b = blockIdx.z, n0 = blockIdx.x * 64, c0 = blockIdx.y * 64;
    const int tid = threadIdx.x;
    if (tid < 64) ssum[tid] = 0.0f;
    __syncthreads();
    for (int i = tid; i < 4096; i += 256) {
        const int n = i >> 6, c = i & 63;
        const size_t go = ((size_t)b * CK_N + n0 + n) * CK_C + c0 + c;
        float v = ctx[go];
        __nv_bfloat16 h = __float2bfloat16(v);
        __nv_bfloat16 l = __float2bfloat16(v - __bfloat162float(h));
        sh[c * 66 + n] = h; sl[c * 66 + n] = l;
        g_c_h[go] = h; g_c_l[go] = l;
        atomicAdd(&ssum[c], v);
    }
    __syncthreads();
    for (int i = tid; i < 4096; i += 256) {
        const int c = i >> 6, n = i & 63;
        const size_t o = ((size_t)b * CK_C + c0 + c) * CK_N + n0 + n;
        g_cT_h[o] = sh[c * 66 + n]; g_cT_l[o] = sl[c * 66 + n];
    }
    if (tid < 64) atomicAdd(&g_sctx[b * CK_C + c0 + tid], ssum[tid]);
}

// ---------------- k_Gmma: G partials (128c x 256c' tile, split-K over n) -----
// grid (4, 2, B*KSPLIT), 512 threads
__global__ __launch_bounds__(512, 1) void k_Gmma() {
    extern __shared__ char smem[];
    const uint32_t sb = smem_u32(smem);
    const int tid = threadIdx.x, lane = tid & 31, wid = tid >> 5;
    const int wm = wid & 3, wn = wid >> 2;
    const int b = blockIdx.z / KSPLIT, ks = blockIdx.z % KSPLIT;
    const int cbase = blockIdx.x * 128, cpbase = blockIdx.y * 256;
    const int nbase = ks * (CK_N / KSPLIT);   // 2048
    const __nv_bfloat16* Ah = g_xT_h + ((size_t)b * CK_C + cbase) * CK_N;
    const __nv_bfloat16* Al = g_xT_l + ((size_t)b * CK_C + cbase) * CK_N;
    const __nv_bfloat16* Bh = g_cT_h + ((size_t)b * CK_C + cpbase) * CK_N;
    const __nv_bfloat16* Bl = g_cT_l + ((size_t)b * CK_C + cpbase) * CK_N;

    float acc[2][8][4];
#pragma unroll
    for (int i = 0; i < 2; i++)
#pragma unroll
        for (int j = 0; j < 8; j++)
#pragma unroll
            for (int q = 0; q < 4; q++) acc[i][j][q] = 0.0f;

    const int NC = (CK_N / KSPLIT) / 64;  // 32
    issue_chunk(sb, Ah, Al, CK_N, Bh, Bl, CK_N, nbase, tid);
    for (int ch = 0; ch < NC; ch++) {
        if (ch + 1 < NC) {
            issue_chunk(sb + ((ch + 1) & 1) * BUF_STRIDE, Ah, Al, CK_N, Bh, Bl, CK_N,
                        nbase + (ch + 1) * 64, tid);
            cp_wait<1>();
        } else {
            cp_wait<0>();
        }
        __syncthreads();
        compute_chunk(sb + (ch & 1) * BUF_STRIDE, wm, wn, lane, acc);
        __syncthreads();
    }

    float* gout = g_Gpart + ((size_t)(b * KSPLIT + ks)) * (CK_C * CK_C);
#pragma unroll
    for (int mt = 0; mt < 2; mt++) {
        const int r0 = cbase + (wm * 2 + mt) * 16 + (lane >> 2);
#pragma unroll
        for (int nt = 0; nt < 8; nt++) {
            const int col = cpbase + (wn * 8 + nt) * 8 + (lane & 3) * 2;
            *(float2*)&gout[(size_t)r0 * CK_C + col] = make_float2(acc[mt][nt][0], acc[mt][nt][1]);
            *(float2*)&gout[(size_t)(r0 + 8) * CK_C + col] = make_float2(acc[mt][nt][2], acc[mt][nt][3]);
        }
    }
}

// ---------------- reduce partials ----------------
__global__ void k_Gred() {
    const int i = blockIdx.x * 256 + threadIdx.x;
    const int per_b4 = CK_C * CK_C / 4;   // 65536 float4s per image
    const int tot4 = CK_B * per_b4;
    for (int j = i; j < tot4; j += gridDim.x * 256) {
        const int b = j / per_b4, w = j % per_b4;
        float4 s = ((const float4*)g_Gpart)[(size_t)(b * KSPLIT) * per_b4 + w];
#pragma unroll
        for (int p = 1; p < KSPLIT; p++) {
            float4 t = ((const float4*)g_Gpart)[(size_t)(b * KSPLIT + p) * per_b4 + w];
            s.x += t.x; s.y += t.y; s.z += t.z; s.w += t.w;
        }
        ((float4*)g_G)[j] = s;
    }
}

// ---------------- k_final: Y = ctx * M^T + r (128n x 256j tile) -------------
// grid (64, 2, B), 512 threads
__global__ __launch_bounds__(512, 1) void k_final(float* __restrict__ Y) {
    extern __shared__ char smem[];
    const uint32_t sb = smem_u32(smem);
    const int tid = threadIdx.x, lane = tid & 31, wid = tid >> 5;
    const int wm = wid & 3, wn = wid >> 2;
    const int b = blockIdx.z;
    const int nb0 = blockIdx.x * 128, jbase = blockIdx.y * 256;
    const __nv_bfloat16* Ah = g_c_h + ((size_t)b * CK_N + nb0) * CK_C;
    const __nv_bfloat16* Al = g_c_l + ((size_t)b * CK_N + nb0) * CK_C;
    const __nv_bfloat16* Bh = g_M_h + ((size_t)b * CK_C + jbase) * CK_C;
    const __nv_bfloat16* Bl = g_M_l + ((size_t)b * CK_C + jbase) * CK_C;

    float acc[2][8][4];
#pragma unroll
    for (int i = 0; i < 2; i++)
#pragma unroll
        for (int j = 0; j < 8; j++)
#pragma unroll
            for (int q = 0; q < 4; q++) acc[i][j][q] = 0.0f;

    const int NC = CK_C / 64;  // 8
    issue_chunk(sb, Ah, Al, CK_C, Bh, Bl, CK_C, 0, tid);
    for (int ch = 0; ch < NC; ch++) {
        if (ch + 1 < NC) {
            issue_chunk(sb + ((ch + 1) & 1) * BUF_STRIDE, Ah, Al, CK_C, Bh, Bl, CK_C,
                        (ch + 1) * 64, tid);
            cp_wait<1>();
        } else {
            cp_wait<0>();
        }
        __syncthreads();
        compute_chunk(sb + (ch & 1) * BUF_STRIDE, wm, wn, lane, acc);
        __syncthreads();
    }

    float* yb = Y + (size_t)b * CK_N * CK_C;
#pragma unroll
    for (int mt = 0; mt < 2; mt++) {
        const int n0 = nb0 + (wm * 2 + mt) * 16 + (lane >> 2);
#pragma unroll
        for (int nt = 0; nt < 8; nt++) {
            const int col = jbase + (wn * 8 + nt) * 8 + (lane & 3) * 2;
            const float r0v = g_r[b * CK_C + col], r1v = g_r[b * CK_C + col + 1];
            *(float2*)&yb[(size_t)n0 * CK_C + col] =
                make_float2(acc[mt][nt][0] + r0v, acc[mt][nt][1] + r1v);
            *(float2*)&yb[(size_t)(n0 + 8) * CK_C + col] =
                make_float2(acc[mt][nt][2] + r0v, acc[mt][nt][3] + r1v);
        }
    }
}

// ---------------- 512^3 fp32 GEMM bodies ----------------
#define GEMM512_PRE() \
    __shared__ float As[64][20]; \
    __shared__ float Bs[16][64]; \
    const int mbase = blockIdx.x * 64, nbase = blockIdx.y * 64; \
    const int tid = threadIdx.x; \
    const int tx = tid & 15, ty = tid >> 4; \
    const int ar = tid >> 2, ac = (tid & 3) << 2; \
    const int br = tid >> 4, bc = (tid & 15) << 2; \
    float acc[4][4]; \
    _Pragma("unroll") for (int i = 0; i < 4; i++) \
    _Pragma("unroll") for (int j = 0; j < 4; j++) acc[i][j] = 0.0f; \
    for (int k0 = 0; k0 < CK_C; k0 += 16) { \
        float4 av = *(const float4*)(A + (size_t)(mbase + ar) * CK_C + k0 + ac); \
        float4 bv = *(const float4*)(Bm + (size_t)(k0 + br) * CK_C + nbase + bc); \
        __syncthreads(); \
        *(float4*)&As[ar][ac] = av; \
        *(float4*)&Bs[br][bc] = bv; \
        __syncthreads(); \
        _Pragma("unroll") for (int kk = 0; kk < 16; kk++) { \
            float a[4], b2[4]; \
            _Pragma("unroll") for (int i = 0; i < 4; i++) a[i] = As[ty + 16 * i][kk]; \
            _Pragma("unroll") for (int j = 0; j < 4; j++) b2[j] = Bs[kk][tx + 16 * j]; \
            _Pragma("unroll") for (int i = 0; i < 4; i++) \
            _Pragma("unroll") for (int j = 0; j < 4; j++) acc[i][j] += a[i] * b2[j]; \
        } \
    }

__global__ __launch_bounds__(256) void k_T1(const float* __restrict__ Wq) {
    const float* A = Wq;
    const float* Bm = g_G + (size_t)blockIdx.z * CK_C * CK_C;
    float* Co = g_T1 + (size_t)blockIdx.z * CK_C * CK_C;
    GEMM512_PRE()
#pragma unroll
    for (int i = 0; i < 4; i++)
#pragma unroll
        for (int j = 0; j < 4; j++)
            Co[(size_t)(mbase + ty + 16 * i) * CK_C + nbase + tx + 16 * j] = acc[i][j];
}
__global__ __launch_bounds__(256) void k_M(const float* __restrict__ Wv) {
    const float* A = g_PA + (size_t)blockIdx.z * CK_C * CK_C;
    const float* Bm = Wv;
    __nv_bfloat16* Mh = g_M_h + (size_t)blockIdx.z * CK_C * CK_C;
    __nv_bfloat16* Ml = g_M_l + (size_t)blockIdx.z * CK_C * CK_C;
    GEMM512_PRE()
#pragma unroll
    for (int i = 0; i < 4; i++)
#pragma unroll
        for (int j = 0; j < 4; j++) {
            const size_t o = (size_t)(mbase + ty + 16 * i) * CK_C + nbase + tx + 16 * j;
            float v = acc[i][j];
            __nv_bfloat16 h = __float2bfloat16(v);
            Mh[o] = h;
            Ml[o] = __float2bfloat16(v - __bfloat162float(h));
        }
}

// ---------------- qrow/krow precompute ----------------
__global__ __launch_bounds__(256) void k_rows(const float* __restrict__ Wq,
                                              const float* __restrict__ Wk) {
    __shared__ float sv[CK_C];
    const int b = blockIdx.x, which = blockIdx.y;
    const float* src = (which ? g_sctx : g_sx) + b * CK_C;
    const float* W = which ? Wk : Wq;
    float* dst = (which ? g_krow : g_qrow) + b * CK_C;
    const int tid = threadIdx.x;
    for (int i = tid; i < CK_C; i += 256) sv[i] = src[i];
    __syncthreads();
    const int w = tid >> 5, l = tid & 31;
    for (int r = w; r < CK_C; r += 8) {
        float s = 0.0f;
        for (int c = l; c < CK_C; c += 32) s += sv[c] * W[(size_t)r * CK_C + c];
#pragma unroll
        for (int o = 16; o; o >>= 1) s += __shfl_xor_sync(0xFFFFFFFFu, s, o);
        if (l == 0) dst[r] = s;
    }
}

// ---------------- att + softmax ----------------
__global__ __launch_bounds__(256) void k_att(const float* __restrict__ Wk,
                                             const float* __restrict__ bq,
                                             const float* __restrict__ bk,
                                             float* __restrict__ out_att) {
    __shared__ float T1s[64][20];
    __shared__ float Wks[64][20];
    __shared__ float S[64][65];
    __shared__ float qrow[64], krow[64], bqs[64], bks[64];
    const int h = blockIdx.x, b = blockIdx.y;
    const int o0 = h * CK_D;
    const int tid = threadIdx.x;
    const int tx = tid & 15, ty = tid >> 4;
    const float* T1b = g_T1 + (size_t)b * CK_C * CK_C;

    if (tid < 64) qrow[tid] = g_qrow[b * CK_C + o0 + tid];
    else if (tid < 128) krow[tid - 64] = g_krow[b * CK_C + o0 + tid - 64];
    else if (tid < 192) bqs[tid - 128] = bq[o0 + tid - 128];
    else bks[tid - 192] = bk[o0 + tid - 192];

    float acc[4][4];
#pragma unroll
    for (int i = 0; i < 4; i++)
#pragma unroll
        for (int j = 0; j < 4; j++) acc[i][j] = 0.0f;
    const int r = tid >> 2, c4 = (tid & 3) << 2;
    for (int k0 = 0; k0 < CK_C; k0 += 16) {
        float4 av = *(const float4*)(T1b + (size_t)(o0 + r) * CK_C + k0 + c4);
        float4 bv = *(const float4*)(Wk + (size_t)(o0 + r) * CK_C + k0 + c4);
        __syncthreads();
        *(float4*)&T1s[r][c4] = av;
        *(float4*)&Wks[r][c4] = bv;
        __syncthreads();
#pragma unroll
        for (int kk = 0; kk < 16; kk++) {
            float a[4], b2[4];
#pragma unroll
            for (int i = 0; i < 4; i++) a[i] = T1s[ty + 16 * i][kk];
#pragma unroll
            for (int j = 0; j < 4; j++) b2[j] = Wks[tx + 16 * j][kk];
#pragma unroll
            for (int i = 0; i < 4; i++)
#pragma unroll
                for (int j = 0; j < 4; j++) acc[i][j] += a[i] * b2[j];
        }
    }
    __syncthreads();
#pragma unroll
    for (int i = 0; i < 4; i++) {
        const int d = ty + 16 * i;
#pragma unroll
        for (int j = 0; j < 4; j++) {
            const int e = tx + 16 * j;
            S[d][e] = CK_SCALE * (acc[i][j] + bqs[d] * krow[e] + bks[e] * qrow[d]
                                  + (float)CK_N * bqs[d] * bks[e]);
        }
    }
    __syncthreads();
    if (tid < 64) {
        const int d = tid;
        float m = -1e30f;
        for (int e = 0; e < 64; e++) m = fmaxf(m, S[d][e]);
        float s = 0.0f;
        for (int e = 0; e < 64; e++) { float p = expf(S[d][e] - m); S[d][e] = p; s += p; }
        const float inv = 1.0f / s;
        float* ga = g_att + (((size_t)b * CK_H + h) * CK_D + d) * CK_D;
        for (int e = 0; e < 64; e++) {
            const float a = S[d][e] * inv;
            ga[e] = a;
            if (out_att) out_att[(((size_t)b * CK_H + h) * CK_D + d) * CK_D + e] = a;
        }
    }
}

// ---------------- PA = proj * blockdiag(att) ----------------
__global__ __launch_bounds__(256) void k_PA(const float* __restrict__ proj) {
    __shared__ float Ps[64][65];
    __shared__ float At[64][65];
    const int jt = blockIdx.x, h = blockIdx.y, b = blockIdx.z;
    const int tid = threadIdx.x;
    for (int i = tid; i < 64 * 64; i += 256) {
        const int rr = i >> 6, cc = i & 63;
        Ps[rr][cc] = proj[(size_t)(jt * 64 + rr) * CK_C + h * 64 + cc];
        At[rr][cc] = g_att[(((size_t)b * CK_H + h) * CK_D + rr) * CK_D + cc];
    }
    __syncthreads();
    const int tx = tid & 15, ty = tid >> 4;
    float acc[4][4];
#pragma unroll
    for (int i = 0; i < 4; i++)
#pragma unroll
        for (int j = 0; j < 4; j++) acc[i][j] = 0.0f;
    for (int d = 0; d < 64; d++) {
        float p[4], a2[4];
#pragma unroll
        for (int i = 0; i < 4; i++) p[i] = Ps[ty + 16 * i][d];
#pragma unroll
        for (int j = 0; j < 4; j++) a2[j] = At[d][tx + 16 * j];
#pragma unroll
        for (int i = 0; i < 4; i++)
#pragma unroll
            for (int j = 0; j < 4; j++) acc[i][j] += p[i] * a2[j];
    }
    float* PAb = g_PA + (size_t)b * CK_C * CK_C;
#pragma unroll
    for (int i = 0; i < 4; i++)
#pragma unroll
        for (int j = 0; j < 4; j++)
            PAb[(size_t)(jt * 64 + ty + 16 * i) * CK_C + h * 64 + tx + 16 * j] = acc[i][j];
}

__global__ void k_r(const float* __restrict__ bv, const float* __restrict__ pb) {
    const int b = blockIdx.x, j = threadIdx.x;
    const float* row = g_PA + ((size_t)b * CK_C + j) * CK_C;
    float s = pb[j];
    for (int o = 0; o < CK_C; o++) s += row[o] * bv[o];
    g_r[b * CK_C + j] = s;
}

// ---------------- launch ----------------
extern "C" void kernel_launch(void* const* d_in, const int* in_sizes, int n_in,
                              void* d_out, int out_size) {
    const float* x    = (const float*)d_in[0];
    const float* ctxp = (const float*)d_in[1];
    const float* Wq_w = (const float*)d_in[2];
    const float* Wq_b = (const float*)d_in[3];
    const float* Wk_w = (const float*)d_in[4];
    const float* Wk_b = (const float*)d_in[5];
    const float* Wv_w = (const float*)d_in[6];
    const float* Wv_b = (const float*)d_in[7];
    const float* Pw   = (const float*)d_in[8];
    const float* Pb   = (const float*)d_in[9];
    float* out = (float*)d_out;

    const int out_elems = CK_B * CK_N * CK_C;
    const int att_elems = CK_B * CK_H * CK_D * CK_D;
    float* att_out = (out_size >= out_elems + att_elems) ? (out + (size_t)out_elems)
                                                         : (float*)0;

    cudaFuncSetAttribute(k_Gmma, cudaFuncAttributeMaxDynamicSharedMemorySize, SMEM_MMA);
    cudaFuncSetAttribute(k_final, cudaFuncAttributeMaxDynamicSharedMemorySize, SMEM_MMA);

    k_zero  <<<8, 256>>>();
    conv_x  <<<dim3(128, 8, CK_B), 256>>>(x);
    conv_ctx<<<dim3(128, 8, CK_B), 256>>>(ctxp);
    k_Gmma  <<<dim3(4, 2, CK_B * KSPLIT), 512, SMEM_MMA>>>();
    k_Gred  <<<512, 256>>>();
    k_T1    <<<dim3(8, 8, CK_B), 256>>>(Wq_w);
    k_rows  <<<dim3(CK_B, 2), 256>>>(Wq_w, Wk_w);
    k_att   <<<dim3(CK_H, CK_B), 256>>>(Wk_w, Wq_b, Wk_b, att_out);
    k_PA    <<<dim3(8, CK_H, CK_B), 256>>>(Pw);
    k_M     <<<dim3(8, 8, CK_B), 256>>>(Wv_w);
    k_r     <<<CK_B, CK_C>>>(Wv_b, Pb);
    k_final <<<dim3(64, 2, CK_B), 512, SMEM_MMA>>>(out);
}